// round 1
// baseline (speedup 1.0000x reference)
#include <cuda_runtime.h>
#include <math.h>

#define NN 100000
#define NE 800000
#define NG 64
#define NT 4
#define D 150
#define HIDN 512
#define PASSES 5
#define NC1 1050      // GEMM1 output cols: 600 (m) + 450 (gh)
#define MLD 1056      // out1 leading dim (padded)
#define GILD 456      // gi leading dim (padded)
#define XLD 152

// ---------------- scratch (device globals; no allocation allowed) ----------
__device__ float g_h[(size_t)NN * D];
__device__ float g_inc[(size_t)NN * D];
__device__ float g_out1[(size_t)NN * MLD];
__device__ float g_gi[(size_t)NN * GILD];
__device__ float g_biasinc[(size_t)NN * D];
__device__ float g_Wbig[NC1 * D];
__device__ float g_bias1[NC1];
__device__ int   g_degt[NN * NT];
__device__ int   g_rowptr[NN + 1];
__device__ int   g_cursor[NN];
__device__ int   g_ebase[NE];
__device__ int   g_gstart[NG + 1];
__device__ float g_x[NG * XLD];

// ---------------- small build kernels ----------------
__global__ void build_wbig(const float* __restrict__ We, const float* __restrict__ whh,
                           float* __restrict__ wbig) {
    int idx = blockIdx.x * blockDim.x + threadIdx.x;
    if (idx >= NC1 * D) return;
    int c = idx / D, j = idx - c * D;
    // c<600: We flat [t][i][j] with c = t*150+i  ->  We[c*150+j]
    wbig[idx] = (c < 600) ? We[idx] : whh[(c - 600) * D + j];
}

__global__ void build_bias1(const float* __restrict__ bhh, float* __restrict__ bias1) {
    int c = blockIdx.x * blockDim.x + threadIdx.x;
    if (c < NC1) bias1[c] = (c < 600) ? 0.f : bhh[c - 600];
}

__global__ void hist_kernel(const int* __restrict__ dst, const int* __restrict__ etype,
                            int* __restrict__ degt, int E) {
    int e = blockIdx.x * blockDim.x + threadIdx.x;
    if (e < E) atomicAdd(&degt[dst[e] * NT + etype[e]], 1);
}

__global__ void biasinc_kernel(const int* __restrict__ degt, const float* __restrict__ be,
                               float* __restrict__ biasinc, int n_nodes) {
    int idx = blockIdx.x * blockDim.x + threadIdx.x;
    if (idx >= n_nodes * D) return;
    int node = idx / D, i = idx - node * D;
    float s = 0.f;
#pragma unroll
    for (int t = 0; t < NT; ++t)
        s += (float)degt[node * NT + t] * be[t * D + i];
    biasinc[idx] = s;
}

// single-block exclusive scan of per-node degree (sum over 4 types)
__global__ void scan_kernel(const int* __restrict__ degt, int* __restrict__ rowptr, int n) {
    __shared__ int warp_tot[32];
    __shared__ int carry_s;
    int tid = threadIdx.x;
    int lane = tid & 31, wid = tid >> 5;
    if (tid == 0) carry_s = 0;
    __syncthreads();
    for (int base = 0; base < n; base += 1024) {
        int idx = base + tid;
        int v = 0;
        if (idx < n)
            v = degt[idx * NT] + degt[idx * NT + 1] + degt[idx * NT + 2] + degt[idx * NT + 3];
        int x = v;
#pragma unroll
        for (int off = 1; off < 32; off <<= 1) {
            int y = __shfl_up_sync(0xffffffffu, x, off);
            if (lane >= off) x += y;
        }
        if (lane == 31) warp_tot[wid] = x;
        __syncthreads();
        if (wid == 0) {
            int w = warp_tot[lane];
            int wx = w;
#pragma unroll
            for (int off = 1; off < 32; off <<= 1) {
                int y = __shfl_up_sync(0xffffffffu, wx, off);
                if (lane >= off) wx += y;
            }
            warp_tot[lane] = wx - w;  // exclusive warp offsets
        }
        __syncthreads();
        int excl = carry_s + warp_tot[wid] + x - v;
        if (idx < n) rowptr[idx] = excl;
        __syncthreads();
        if (tid == 1023) carry_s = excl + v;
        __syncthreads();
    }
    if (tid == 0) rowptr[n] = carry_s;
}

__global__ void csr_fill(const int* __restrict__ src, const int* __restrict__ dst,
                         const int* __restrict__ etype, int* __restrict__ cursor,
                         int* __restrict__ ebase, int E) {
    int e = blockIdx.x * blockDim.x + threadIdx.x;
    if (e >= E) return;
    int pos = atomicAdd(&cursor[dst[e]], 1);
    ebase[pos] = src[e] * MLD + etype[e] * D;  // base offset into out1's m-part
}

// ---------------- SGEMM: C[M,N] = A[M,K] @ B[N,K]^T + bias[N] ---------------
#define BM 128
#define BN 128
#define KC 25
#define TM 8
#define TN 8

__global__ __launch_bounds__(256) void sgemm_bias(
    const float* __restrict__ A, int lda,
    const float* __restrict__ B, int ldb,
    float* __restrict__ C, int ldc,
    int M, int N, int K,
    const float* __restrict__ bias) {
    __shared__ float As[KC][BM + 4];
    __shared__ float Bs[KC][BN + 4];
    int tid = threadIdx.x;
    int tx = tid & 15, ty = tid >> 4;
    int m0 = blockIdx.y * BM;
    int n0 = blockIdx.x * BN;

    float acc[TM][TN];
#pragma unroll
    for (int i = 0; i < TM; ++i)
#pragma unroll
        for (int j = 0; j < TN; ++j) acc[i][j] = 0.f;

    for (int k0 = 0; k0 < K; k0 += KC) {
        for (int idx = tid; idx < BM * KC; idx += 256) {
            int kk = idx % KC, m = idx / KC;
            int gm = m0 + m, gk = k0 + kk;
            As[kk][m] = (gm < M && gk < K) ? A[(size_t)gm * lda + gk] : 0.f;
        }
        for (int idx = tid; idx < BN * KC; idx += 256) {
            int kk = idx % KC, n = idx / KC;
            int gn = n0 + n, gk = k0 + kk;
            Bs[kk][n] = (gn < N && gk < K) ? B[(size_t)gn * ldb + gk] : 0.f;
        }
        __syncthreads();
#pragma unroll
        for (int k = 0; k < KC; ++k) {
            float4 a0 = *(const float4*)&As[k][ty * TM];
            float4 a1 = *(const float4*)&As[k][ty * TM + 4];
            float4 b0 = *(const float4*)&Bs[k][tx * TN];
            float4 b1 = *(const float4*)&Bs[k][tx * TN + 4];
            float a[TM] = {a0.x, a0.y, a0.z, a0.w, a1.x, a1.y, a1.z, a1.w};
            float b[TN] = {b0.x, b0.y, b0.z, b0.w, b1.x, b1.y, b1.z, b1.w};
#pragma unroll
            for (int i = 0; i < TM; ++i)
#pragma unroll
                for (int j = 0; j < TN; ++j) acc[i][j] += a[i] * b[j];
        }
        __syncthreads();
    }

#pragma unroll
    for (int i = 0; i < TM; ++i) {
        int gm = m0 + ty * TM + i;
        if (gm >= M) continue;
#pragma unroll
        for (int j = 0; j < TN; ++j) {
            int gn = n0 + tx * TN + j;
            if (gn < N) C[(size_t)gm * ldc + gn] = acc[i][j] + (bias ? bias[gn] : 0.f);
        }
    }
}

// ---------------- CSR gather-aggregate ----------------
__global__ void aggregate(const float* __restrict__ m, const float* __restrict__ biasinc,
                          const int* __restrict__ rowptr, const int* __restrict__ ebase,
                          float* __restrict__ inc) {
    int node = blockIdx.x;
    int i = threadIdx.x;
    if (i >= D) return;
    int s = rowptr[node], e = rowptr[node + 1];
    float acc = biasinc[(size_t)node * D + i];
    for (int p = s; p < e; ++p)
        acc += m[(size_t)ebase[p] + i];
    inc[(size_t)node * D + i] = acc;
}

// ---------------- GRU elementwise ----------------
__global__ void gru_kernel(const float* __restrict__ gi, const float* __restrict__ o1,
                           float* __restrict__ h, int n_nodes) {
    int idx = blockIdx.x * blockDim.x + threadIdx.x;
    if (idx >= n_nodes * D) return;
    int node = idx / D, i = idx - node * D;
    const float* gir = gi + (size_t)node * GILD;
    const float* ghr = o1 + (size_t)node * MLD + 600;
    float ir = gir[i], iz = gir[D + i], inn = gir[2 * D + i];
    float hr = ghr[i], hz = ghr[D + i], hn = ghr[2 * D + i];
    float r = 1.f / (1.f + expf(-(ir + hr)));
    float z = 1.f / (1.f + expf(-(iz + hz)));
    float nn = tanhf(inn + r * hn);
    h[idx] = (1.f - z) * nn + z * h[idx];
}

// ---------------- readout + MLP ----------------
__global__ void gstart_init(int* __restrict__ gstart, int n_nodes) {
    int g = threadIdx.x;
    if (g <= NG) gstart[g] = (g == NG) ? n_nodes : 0x7fffffff;
}
__global__ void gstart_min(const int* __restrict__ gids, int* __restrict__ gstart, int n) {
    int i = blockIdx.x * blockDim.x + threadIdx.x;
    if (i < n) atomicMin(&gstart[gids[i]], i);
}
__global__ void gstart_fix(int* __restrict__ gstart) {
    if (threadIdx.x == 0)
        for (int g = NG - 1; g >= 0; --g)
            if (gstart[g] == 0x7fffffff) gstart[g] = gstart[g + 1];
}

__global__ void readout(const float* __restrict__ h, const int* __restrict__ gstart,
                        const float* __restrict__ pclass, float* __restrict__ x) {
    int g = blockIdx.x;
    int i = threadIdx.x;
    int s = gstart[g], e = gstart[g + 1];
    if (i < D) {
        float acc = 0.f;
        for (int n = s; n < e; ++n) acc += h[(size_t)n * D + i];
        float l = logf(acc);
        if (l != l) l = 0.f;      // NaN -> 0
        l = fmaxf(l, 0.f);        // relu (also kills -inf)
        x[g * XLD + i] = l;
    }
    if (i == D) x[g * XLD + D] = pclass[g];
}

__global__ void mlp_kernel(const float* __restrict__ x,
                           const float* __restrict__ fc1w, const float* __restrict__ fc1b,
                           const float* __restrict__ fc2w, const float* __restrict__ fc2b,
                           float* __restrict__ out) {
    __shared__ float xb[D + 1];
    __shared__ float hid[HIDN];
    int g = blockIdx.x, t = threadIdx.x;
    if (t < D + 1) xb[t] = x[g * XLD + t];
    __syncthreads();
    float acc = fc1b[t];
    for (int k = 0; k < D + 1; ++k) acc += xb[k] * fc1w[k * HIDN + t];
    hid[t] = acc > 0.f ? acc : 0.01f * acc;  // leaky_relu(0.01)
    __syncthreads();
    if (t < 10) {
        float o = fc2b[t];
        for (int k = 0; k < HIDN; ++k) o += hid[k] * fc2w[k * 10 + t];
        out[g * 10 + t] = o;
    }
}

// ---------------- launch ----------------
extern "C" void kernel_launch(void* const* d_in, const int* in_sizes, int n_in,
                              void* d_out, int out_size) {
    const float* nodes  = (const float*)d_in[0];
    const float* pclass = (const float*)d_in[1];
    const int*   esrc   = (const int*)d_in[2];
    const int*   edst   = (const int*)d_in[3];
    const int*   etype  = (const int*)d_in[4];
    const int*   gids   = (const int*)d_in[5];
    const float* We     = (const float*)d_in[6];
    const float* be     = (const float*)d_in[7];
    const float* wih    = (const float*)d_in[8];
    const float* whh    = (const float*)d_in[9];
    const float* bih    = (const float*)d_in[10];
    const float* bhh    = (const float*)d_in[11];
    const float* fc1w   = (const float*)d_in[12];
    const float* fc1b   = (const float*)d_in[13];
    const float* fc2w   = (const float*)d_in[14];
    const float* fc2b   = (const float*)d_in[15];
    float* out = (float*)d_out;

    int n_nodes = in_sizes[0] / D;
    int E = in_sizes[2];

    float *h_p, *inc_p, *o1_p, *gi_p, *bi_p, *wbig_p, *b1_p, *x_p;
    int *degt_p, *rowptr_p, *cursor_p, *ebase_p, *gstart_p;
    cudaGetSymbolAddress((void**)&h_p, g_h);
    cudaGetSymbolAddress((void**)&inc_p, g_inc);
    cudaGetSymbolAddress((void**)&o1_p, g_out1);
    cudaGetSymbolAddress((void**)&gi_p, g_gi);
    cudaGetSymbolAddress((void**)&bi_p, g_biasinc);
    cudaGetSymbolAddress((void**)&wbig_p, g_Wbig);
    cudaGetSymbolAddress((void**)&b1_p, g_bias1);
    cudaGetSymbolAddress((void**)&x_p, g_x);
    cudaGetSymbolAddress((void**)&degt_p, g_degt);
    cudaGetSymbolAddress((void**)&rowptr_p, g_rowptr);
    cudaGetSymbolAddress((void**)&cursor_p, g_cursor);
    cudaGetSymbolAddress((void**)&ebase_p, g_ebase);
    cudaGetSymbolAddress((void**)&gstart_p, g_gstart);

    // one-time per call: degree histogram, bias_inc, Wbig, bias1, CSR
    cudaMemsetAsync(degt_p, 0, sizeof(int) * (size_t)n_nodes * NT);
    hist_kernel<<<(E + 255) / 256, 256>>>(edst, etype, degt_p, E);
    biasinc_kernel<<<(n_nodes * D + 255) / 256, 256>>>(degt_p, be, bi_p, n_nodes);
    build_wbig<<<(NC1 * D + 255) / 256, 256>>>(We, whh, wbig_p);
    build_bias1<<<(NC1 + 255) / 256, 256>>>(bhh, b1_p);
    scan_kernel<<<1, 1024>>>(degt_p, rowptr_p, n_nodes);
    cudaMemcpyAsync(cursor_p, rowptr_p, sizeof(int) * (size_t)n_nodes,
                    cudaMemcpyDeviceToDevice);
    csr_fill<<<(E + 255) / 256, 256>>>(esrc, edst, etype, cursor_p, ebase_p, E);
    cudaMemcpyAsync(h_p, nodes, sizeof(float) * (size_t)n_nodes * D,
                    cudaMemcpyDeviceToDevice);

    dim3 g1((NC1 + BN - 1) / BN, (n_nodes + BM - 1) / BM);
    dim3 g2((450 + BN - 1) / BN, (n_nodes + BM - 1) / BM);
    for (int p = 0; p < PASSES; ++p) {
        // out1[:, :600] = m (4 edge-type transforms), out1[:, 600:1050] = gh + b_hh
        sgemm_bias<<<g1, 256>>>(h_p, D, wbig_p, D, o1_p, MLD, n_nodes, NC1, D, b1_p);
        aggregate<<<n_nodes, 160>>>(o1_p, bi_p, rowptr_p, ebase_p, inc_p);
        sgemm_bias<<<g2, 256>>>(inc_p, D, wih, D, gi_p, GILD, n_nodes, 450, D, bih);
        gru_kernel<<<(n_nodes * D + 255) / 256, 256>>>(gi_p, o1_p, h_p, n_nodes);
    }

    gstart_init<<<1, NG + 1>>>(gstart_p, n_nodes);
    gstart_min<<<(n_nodes + 255) / 256, 256>>>(gids, gstart_p, n_nodes);
    gstart_fix<<<1, 1>>>(gstart_p);
    readout<<<NG, 160>>>(h_p, gstart_p, pclass, x_p);
    mlp_kernel<<<NG, HIDN>>>(x_p, fc1w, fc1b, fc2w, fc2b, out);
}

// round 3
// speedup vs baseline: 1.0382x; 1.0382x over previous
#include <cuda_runtime.h>
#include <math.h>
#include <stdint.h>

#define NN 100000
#define NE 800000
#define NG 64
#define NT 4
#define D 150
#define HIDN 512
#define PASSES 5
#define NC1 1050      // GEMM1 output cols: 600 (m) + 450 (gh)
#define MLD 1056      // out1 leading dim (padded)
#define GILD 456      // gi leading dim (padded)
#define XLD 152
#define KLD 160       // padded K stride for GEMM A/B operands (zeros in 150..159)

// ---------------- scratch (device globals; no allocation allowed) ----------
__device__ float g_h[(size_t)NN * KLD];
__device__ float g_inc[(size_t)NN * KLD];
__device__ float g_out1[(size_t)NN * MLD];
__device__ float g_gi[(size_t)NN * GILD];
__device__ float g_biasinc[(size_t)NN * D];
__device__ float g_Wbig[NC1 * KLD];
__device__ float g_wih[450 * KLD];
__device__ float g_bias1[NC1];
__device__ int   g_degt[NN * NT];
__device__ int   g_rowptr[NN + 1];
__device__ int   g_cursor[NN];
__device__ int   g_ebase[NE];
__device__ int   g_gstart[NG + 1];
__device__ float g_x[NG * XLD];

// ---------------- fused setup: zero degt, build padded Wbig/wih, bias1 -----
__global__ void setup_weights(const float* __restrict__ We, const float* __restrict__ whh,
                              const float* __restrict__ wih,
                              const float* __restrict__ bhh,
                              float* __restrict__ wbig, float* __restrict__ wihp,
                              float* __restrict__ bias1, int* __restrict__ degt) {
    int idx = blockIdx.x * blockDim.x + threadIdx.x;
    if (idx < NN * NT) { degt[idx] = 0; return; }
    idx -= NN * NT;
    if (idx < NC1 * KLD) {
        int c = idx / KLD, j = idx - c * KLD;
        float v = 0.f;
        if (j < D) v = (c < 600) ? We[c * D + j] : whh[(c - 600) * D + j];
        wbig[idx] = v;
        return;
    }
    idx -= NC1 * KLD;
    if (idx < 450 * KLD) {
        int c = idx / KLD, j = idx - c * KLD;
        wihp[idx] = (j < D) ? wih[c * D + j] : 0.f;
        return;
    }
    idx -= 450 * KLD;
    if (idx < NC1) bias1[idx] = (idx < 600) ? 0.f : bhh[idx - 600];
}

// copy nodes -> g_h (padded) and zero g_inc padding columns
__global__ void copy_h(const float* __restrict__ nodes, float* __restrict__ h,
                       float* __restrict__ inc) {
    int idx = blockIdx.x * blockDim.x + threadIdx.x;
    if (idx < NN * KLD) {
        int node = idx / KLD, c = idx - node * KLD;
        h[idx] = (c < D) ? nodes[node * D + c] : 0.f;
        return;
    }
    idx -= NN * KLD;
    if (idx < NN * (KLD - D)) {
        int node = idx / (KLD - D), c = D + idx % (KLD - D);
        inc[node * KLD + c] = 0.f;
    }
}

__global__ void hist_kernel(const int* __restrict__ dst, const int* __restrict__ etype,
                            int* __restrict__ degt, int E) {
    int e = blockIdx.x * blockDim.x + threadIdx.x;
    if (e < E) atomicAdd(&degt[dst[e] * NT + etype[e]], 1);
}

__global__ void biasinc_kernel(const int* __restrict__ degt, const float* __restrict__ be,
                               float* __restrict__ biasinc, int n_nodes) {
    int idx = blockIdx.x * blockDim.x + threadIdx.x;
    if (idx >= n_nodes * D) return;
    int node = idx / D, i = idx - node * D;
    float s = 0.f;
#pragma unroll
    for (int t = 0; t < NT; ++t)
        s += (float)degt[node * NT + t] * be[t * D + i];
    biasinc[idx] = s;
}

// single-block exclusive scan; also writes cursor copy
__global__ void scan_kernel(const int* __restrict__ degt, int* __restrict__ rowptr,
                            int* __restrict__ cursor, int n) {
    __shared__ int warp_tot[32];
    __shared__ int carry_s;
    int tid = threadIdx.x;
    int lane = tid & 31, wid = tid >> 5;
    if (tid == 0) carry_s = 0;
    __syncthreads();
    for (int base = 0; base < n; base += 1024) {
        int idx = base + tid;
        int v = 0;
        if (idx < n)
            v = degt[idx * NT] + degt[idx * NT + 1] + degt[idx * NT + 2] + degt[idx * NT + 3];
        int x = v;
#pragma unroll
        for (int off = 1; off < 32; off <<= 1) {
            int y = __shfl_up_sync(0xffffffffu, x, off);
            if (lane >= off) x += y;
        }
        if (lane == 31) warp_tot[wid] = x;
        __syncthreads();
        if (wid == 0) {
            int w = warp_tot[lane];
            int wx = w;
#pragma unroll
            for (int off = 1; off < 32; off <<= 1) {
                int y = __shfl_up_sync(0xffffffffu, wx, off);
                if (lane >= off) wx += y;
            }
            warp_tot[lane] = wx - w;
        }
        __syncthreads();
        int excl = carry_s + warp_tot[wid] + x - v;
        if (idx < n) { rowptr[idx] = excl; cursor[idx] = excl; }
        __syncthreads();
        if (tid == 1023) carry_s = excl + v;
        __syncthreads();
    }
    if (tid == 0) rowptr[n] = carry_s;
}

__global__ void csr_fill(const int* __restrict__ src, const int* __restrict__ dst,
                         const int* __restrict__ etype, int* __restrict__ cursor,
                         int* __restrict__ ebase, int E) {
    int e = blockIdx.x * blockDim.x + threadIdx.x;
    if (e >= E) return;
    int pos = atomicAdd(&cursor[dst[e]], 1);
    ebase[pos] = src[e] * MLD + etype[e] * D;
}

// ---------------- 3xTF32 tensor-core GEMM ----------------
// C[M,N] = A[M,K]@B[N,K]^T + bias[N], K fixed = 160 (zero padded), lda=ldb=KLD
// Each fp32 split: hi = tf32(x), lo = tf32(x - hi). Product = hi*hi + hi*lo + lo*hi
// (lo*lo dropped: ~2^-22 relative). fp32-level accuracy on the tensor pipe.
#define KC 32
#define KSTEPS 4
#define NCHUNK 5

__device__ __forceinline__ uint32_t f2tf32(float f) {
    uint32_t u;
    asm("cvt.rna.tf32.f32 %0, %1;" : "=r"(u) : "f"(f));
    return u;
}

__device__ __forceinline__ void mma_tf32(float* d, const uint32_t* a, const uint32_t* b) {
    asm volatile(
        "mma.sync.aligned.m16n8k8.row.col.f32.tf32.tf32.f32 "
        "{%0,%1,%2,%3}, {%4,%5,%6,%7}, {%8,%9}, {%0,%1,%2,%3};"
        : "+f"(d[0]), "+f"(d[1]), "+f"(d[2]), "+f"(d[3])
        : "r"(a[0]), "r"(a[1]), "r"(a[2]), "r"(a[3]), "r"(b[0]), "r"(b[1]));
}

#define AIDX(ks, mt, ln, rg) ((((ks) * 8 + (mt)) * 32 + (ln)) * 4 + (rg))
#define BIDX(ks, nt, ln, rg) ((((ks) * 16 + (nt)) * 32 + (ln)) * 2 + (rg))
#define SM_A 4096   // u32 count of one A stage array
#define SM_B 4096

__global__ __launch_bounds__(256) void gemm_3xtf32(
    const float* __restrict__ A,
    const float* __restrict__ B,
    float* __restrict__ C, int ldc,
    int M, int N, const float* __restrict__ bias) {
    extern __shared__ uint32_t sm[];
    uint32_t* As_hi = sm;
    uint32_t* As_lo = sm + SM_A;
    uint32_t* Bs_hi = sm + 2 * SM_A;
    uint32_t* Bs_lo = sm + 2 * SM_A + SM_B;

    int tid = threadIdx.x;
    int lane = tid & 31, wid = tid >> 5;
    int wm = wid & 1, wn = wid >> 1;  // 2x4 warp grid
    int m0 = blockIdx.y * 128, n0 = blockIdx.x * 128;

    float acc[4][4][4];
#pragma unroll
    for (int i = 0; i < 4; ++i)
#pragma unroll
        for (int j = 0; j < 4; ++j)
#pragma unroll
            for (int r = 0; r < 4; ++r) acc[i][j][r] = 0.f;

    int ra = tid >> 1;      // row handled in staging (0..127)
    int qa = tid & 1;       // which 16-col half of the 32-col chunk

    // A staging decomposition
    int a_mt = ra >> 4;
    int a_r = ra & 15;
    int a_lbase = (a_r & 7) * 4;
    int a_rbase = a_r >> 3;
    // B staging decomposition
    int b_nt = ra >> 3;
    int b_lbase = (ra & 7) * 4;

    for (int kc = 0; kc < NCHUNK; ++kc) {
        int k0 = kc * KC;
        // ---- stage A (hi + lo) ----
        {
            int gm = m0 + ra;
            const float4* srcp = (const float4*)(A + (size_t)gm * KLD + k0 + qa * 16);
#pragma unroll
            for (int q = 0; q < 4; ++q) {
                float4 v = make_float4(0.f, 0.f, 0.f, 0.f);
                if (gm < M) v = srcp[q];
                int kk = qa * 16 + q * 4;
                int ks = kk >> 3;
                int reg = a_rbase + (((kk & 7) >= 4) ? 2 : 0);
                int base = AIDX(ks, a_mt, a_lbase, reg);
                uint32_t hx = f2tf32(v.x), hy = f2tf32(v.y);
                uint32_t hz = f2tf32(v.z), hw = f2tf32(v.w);
                As_hi[base + 0]  = hx;
                As_hi[base + 4]  = hy;
                As_hi[base + 8]  = hz;
                As_hi[base + 12] = hw;
                As_lo[base + 0]  = f2tf32(v.x - __uint_as_float(hx));
                As_lo[base + 4]  = f2tf32(v.y - __uint_as_float(hy));
                As_lo[base + 8]  = f2tf32(v.z - __uint_as_float(hz));
                As_lo[base + 12] = f2tf32(v.w - __uint_as_float(hw));
            }
        }
        // ---- stage B (hi + lo) ----
        {
            int gn = n0 + ra;
            const float4* srcp = (const float4*)(B + (size_t)gn * KLD + k0 + qa * 16);
#pragma unroll
            for (int q = 0; q < 4; ++q) {
                float4 v = make_float4(0.f, 0.f, 0.f, 0.f);
                if (gn < N) v = srcp[q];
                int kk = qa * 16 + q * 4;
                int ks = kk >> 3;
                int reg = ((kk & 7) >= 4) ? 1 : 0;
                int base = BIDX(ks, b_nt, b_lbase, reg);
                uint32_t hx = f2tf32(v.x), hy = f2tf32(v.y);
                uint32_t hz = f2tf32(v.z), hw = f2tf32(v.w);
                Bs_hi[base + 0] = hx;
                Bs_hi[base + 2] = hy;
                Bs_hi[base + 4] = hz;
                Bs_hi[base + 6] = hw;
                Bs_lo[base + 0] = f2tf32(v.x - __uint_as_float(hx));
                Bs_lo[base + 2] = f2tf32(v.y - __uint_as_float(hy));
                Bs_lo[base + 4] = f2tf32(v.z - __uint_as_float(hz));
                Bs_lo[base + 6] = f2tf32(v.w - __uint_as_float(hw));
            }
        }
        __syncthreads();
        // ---- compute: 3 MMAs per (mt,nt) per ks ----
#pragma unroll
        for (int ks = 0; ks < KSTEPS; ++ks) {
            uint32_t ah[4][4], al[4][4];
            uint32_t bh[4][2], bl[4][2];
#pragma unroll
            for (int mt = 0; mt < 4; ++mt) {
                uint4 t = *(const uint4*)&As_hi[AIDX(ks, wm * 4 + mt, lane, 0)];
                ah[mt][0] = t.x; ah[mt][1] = t.y; ah[mt][2] = t.z; ah[mt][3] = t.w;
                uint4 u = *(const uint4*)&As_lo[AIDX(ks, wm * 4 + mt, lane, 0)];
                al[mt][0] = u.x; al[mt][1] = u.y; al[mt][2] = u.z; al[mt][3] = u.w;
            }
#pragma unroll
            for (int nt = 0; nt < 4; ++nt) {
                uint2 t = *(const uint2*)&Bs_hi[BIDX(ks, wn * 4 + nt, lane, 0)];
                bh[nt][0] = t.x; bh[nt][1] = t.y;
                uint2 u = *(const uint2*)&Bs_lo[BIDX(ks, wn * 4 + nt, lane, 0)];
                bl[nt][0] = u.x; bl[nt][1] = u.y;
            }
#pragma unroll
            for (int mt = 0; mt < 4; ++mt)
#pragma unroll
                for (int nt = 0; nt < 4; ++nt) {
                    mma_tf32(acc[mt][nt], ah[mt], bl[nt]);
                    mma_tf32(acc[mt][nt], al[mt], bh[nt]);
                    mma_tf32(acc[mt][nt], ah[mt], bh[nt]);
                }
        }
        __syncthreads();
    }

    // ---- epilogue ----
    int gi_ = lane >> 2, ti = lane & 3;
#pragma unroll
    for (int mt = 0; mt < 4; ++mt) {
#pragma unroll
        for (int nt = 0; nt < 4; ++nt) {
            int row = m0 + wm * 64 + mt * 16 + gi_;
            int col = n0 + wn * 32 + nt * 8 + 2 * ti;
            if (col >= N) continue;
            float b0 = bias[col], b1 = bias[col + 1];
            if (row < M) {
                float2 v = make_float2(acc[mt][nt][0] + b0, acc[mt][nt][1] + b1);
                *(float2*)&C[(size_t)row * ldc + col] = v;
            }
            if (row + 8 < M) {
                float2 v = make_float2(acc[mt][nt][2] + b0, acc[mt][nt][3] + b1);
                *(float2*)&C[(size_t)(row + 8) * ldc + col] = v;
            }
        }
    }
}

// ---------------- CSR gather-aggregate ----------------
__global__ void aggregate(const float* __restrict__ m, const float* __restrict__ biasinc,
                          const int* __restrict__ rowptr, const int* __restrict__ ebase,
                          float* __restrict__ inc) {
    int node = blockIdx.x;
    int i = threadIdx.x;
    if (i >= D) return;
    int s = rowptr[node], e = rowptr[node + 1];
    float acc = biasinc[(size_t)node * D + i];
    for (int p = s; p < e; ++p)
        acc += m[(size_t)ebase[p] + i];
    inc[(size_t)node * KLD + i] = acc;
}

// ---------------- GRU elementwise ----------------
__global__ void gru_kernel(const float* __restrict__ gi, const float* __restrict__ o1,
                           float* __restrict__ h, int n_nodes) {
    int idx = blockIdx.x * blockDim.x + threadIdx.x;
    if (idx >= n_nodes * D) return;
    int node = idx / D, i = idx - node * D;
    const float* gir = gi + (size_t)node * GILD;
    const float* ghr = o1 + (size_t)node * MLD + 600;
    float ir = gir[i], iz = gir[D + i], inn = gir[2 * D + i];
    float hr = ghr[i], hz = ghr[D + i], hn = ghr[2 * D + i];
    float r = 1.f / (1.f + expf(-(ir + hr)));
    float z = 1.f / (1.f + expf(-(iz + hz)));
    float nn = tanhf(inn + r * hn);
    size_t hidx = (size_t)node * KLD + i;
    h[hidx] = (1.f - z) * nn + z * h[hidx];
}

// ---------------- readout + MLP ----------------
__global__ void gstart_init(int* __restrict__ gstart, int n_nodes) {
    int g = threadIdx.x;
    if (g <= NG) gstart[g] = (g == NG) ? n_nodes : 0x7fffffff;
}
__global__ void gstart_min(const int* __restrict__ gids, int* __restrict__ gstart, int n) {
    int i = blockIdx.x * blockDim.x + threadIdx.x;
    if (i < n) atomicMin(&gstart[gids[i]], i);
}
__global__ void gstart_fix(int* __restrict__ gstart) {
    if (threadIdx.x == 0)
        for (int g = NG - 1; g >= 0; --g)
            if (gstart[g] == 0x7fffffff) gstart[g] = gstart[g + 1];
}

__global__ void readout(const float* __restrict__ h, const int* __restrict__ gstart,
                        const float* __restrict__ pclass, float* __restrict__ x) {
    int g = blockIdx.x;
    int i = threadIdx.x;
    int s = gstart[g], e = gstart[g + 1];
    if (i < D) {
        float acc = 0.f;
        for (int n = s; n < e; ++n) acc += h[(size_t)n * KLD + i];
        float l = logf(acc);
        if (l != l) l = 0.f;
        l = fmaxf(l, 0.f);
        x[g * XLD + i] = l;
    }
    if (i == D) x[g * XLD + D] = pclass[g];
}

__global__ void mlp_kernel(const float* __restrict__ x,
                           const float* __restrict__ fc1w, const float* __restrict__ fc1b,
                           const float* __restrict__ fc2w, const float* __restrict__ fc2b,
                           float* __restrict__ out) {
    __shared__ float xb[D + 1];
    __shared__ float hid[HIDN];
    int g = blockIdx.x, t = threadIdx.x;
    if (t < D + 1) xb[t] = x[g * XLD + t];
    __syncthreads();
    float acc = fc1b[t];
    for (int k = 0; k < D + 1; ++k) acc += xb[k] * fc1w[k * HIDN + t];
    hid[t] = acc > 0.f ? acc : 0.01f * acc;
    __syncthreads();
    if (t < 10) {
        float o = fc2b[t];
        for (int k = 0; k < HIDN; ++k) o += hid[k] * fc2w[k * 10 + t];
        out[g * 10 + t] = o;
    }
}

// ---------------- launch ----------------
extern "C" void kernel_launch(void* const* d_in, const int* in_sizes, int n_in,
                              void* d_out, int out_size) {
    const float* nodes  = (const float*)d_in[0];
    const float* pclass = (const float*)d_in[1];
    const int*   esrc   = (const int*)d_in[2];
    const int*   edst   = (const int*)d_in[3];
    const int*   etype  = (const int*)d_in[4];
    const int*   gids   = (const int*)d_in[5];
    const float* We     = (const float*)d_in[6];
    const float* be     = (const float*)d_in[7];
    const float* wih    = (const float*)d_in[8];
    const float* whh    = (const float*)d_in[9];
    const float* bih    = (const float*)d_in[10];
    const float* bhh    = (const float*)d_in[11];
    const float* fc1w   = (const float*)d_in[12];
    const float* fc1b   = (const float*)d_in[13];
    const float* fc2w   = (const float*)d_in[14];
    const float* fc2b   = (const float*)d_in[15];
    float* out = (float*)d_out;

    int n_nodes = in_sizes[0] / D;
    int E = in_sizes[2];

    float *h_p, *inc_p, *o1_p, *gi_p, *bi_p, *wbig_p, *wih_p, *b1_p, *x_p;
    int *degt_p, *rowptr_p, *cursor_p, *ebase_p, *gstart_p;
    cudaGetSymbolAddress((void**)&h_p, g_h);
    cudaGetSymbolAddress((void**)&inc_p, g_inc);
    cudaGetSymbolAddress((void**)&o1_p, g_out1);
    cudaGetSymbolAddress((void**)&gi_p, g_gi);
    cudaGetSymbolAddress((void**)&bi_p, g_biasinc);
    cudaGetSymbolAddress((void**)&wbig_p, g_Wbig);
    cudaGetSymbolAddress((void**)&wih_p, g_wih);
    cudaGetSymbolAddress((void**)&b1_p, g_bias1);
    cudaGetSymbolAddress((void**)&x_p, g_x);
    cudaGetSymbolAddress((void**)&degt_p, g_degt);
    cudaGetSymbolAddress((void**)&rowptr_p, g_rowptr);
    cudaGetSymbolAddress((void**)&cursor_p, g_cursor);
    cudaGetSymbolAddress((void**)&ebase_p, g_ebase);
    cudaGetSymbolAddress((void**)&gstart_p, g_gstart);

    static int smem_set = 0;
    if (!smem_set) {
        cudaFuncSetAttribute(gemm_3xtf32, cudaFuncAttributeMaxDynamicSharedMemorySize,
                             (2 * SM_A + 2 * SM_B) * 4);
        smem_set = 1;
    }

    // setup (kernel-launch indices 0..4; GEMM1 of pass 0 lands at index 5 for ncu -s 5)
    int setup_items = NN * NT + NC1 * KLD + 450 * KLD + NC1;
    setup_weights<<<(setup_items + 255) / 256, 256>>>(We, whh, wih, bhh,
                                                      wbig_p, wih_p, b1_p, degt_p);
    int copy_items = NN * KLD + NN * (KLD - D);
    copy_h<<<(copy_items + 255) / 256, 256>>>(nodes, h_p, inc_p);
    hist_kernel<<<(E + 255) / 256, 256>>>(edst, etype, degt_p, E);
    scan_kernel<<<1, 1024>>>(degt_p, rowptr_p, cursor_p, n_nodes);
    biasinc_kernel<<<(n_nodes * D + 255) / 256, 256>>>(degt_p, be, bi_p, n_nodes);

    dim3 g1((NC1 + 127) / 128, (n_nodes + 127) / 128);
    dim3 g2((450 + 127) / 128, (n_nodes + 127) / 128);
    size_t smem_bytes = (2 * SM_A + 2 * SM_B) * 4;

    for (int p = 0; p < PASSES; ++p) {
        gemm_3xtf32<<<g1, 256, smem_bytes>>>(h_p, wbig_p, o1_p, MLD, n_nodes, NC1, b1_p);
        if (p == 0)
            csr_fill<<<(E + 255) / 256, 256>>>(esrc, edst, etype, cursor_p, ebase_p, E);
        aggregate<<<n_nodes, 160>>>(o1_p, bi_p, rowptr_p, ebase_p, inc_p);
        gemm_3xtf32<<<g2, 256, smem_bytes>>>(inc_p, wih_p, gi_p, GILD, n_nodes, 450, bih);
        gru_kernel<<<(n_nodes * D + 255) / 256, 256>>>(gi_p, o1_p, h_p, n_nodes);
    }

    gstart_init<<<1, NG + 1>>>(gstart_p, n_nodes);
    gstart_min<<<(n_nodes + 255) / 256, 256>>>(gids, gstart_p, n_nodes);
    gstart_fix<<<1, 1>>>(gstart_p);
    readout<<<NG, 160>>>(h_p, gstart_p, pclass, x_p);
    mlp_kernel<<<NG, HIDN>>>(x_p, fc1w, fc1b, fc2w, fc2b, out);
}